// round 1
// baseline (speedup 1.0000x reference)
#include <cuda_runtime.h>

// ACDA dynamic convolution, fp32 FFMA baseline.
// B=8, C=64, H=W=128, K=3. out[b,c,h,w] = sum_p relu(W[c*9+p,:]·x[b,:,h,w] + b[c*9+p]) * x[b,c,h+dh,w+dw]
static constexpr int C    = 64;
static constexpr int Hd   = 128;
static constexpr int Wd   = 128;
static constexpr int OKK  = C * 9;                     // 576
static constexpr int SMEM_FLOATS = OKK * C + C * Wd;   // 36864 + 8192
static constexpr int SMEM_BYTES  = SMEM_FLOATS * 4;    // 180224

__global__ __launch_bounds__(256, 1)
void acda_kernel(const float* __restrict__ x,
                 const float* __restrict__ Wg,
                 const float* __restrict__ bg,
                 float* __restrict__ out)
{
    extern __shared__ float smem[];
    float* Ws = smem;             // [576][64]  filter-generator weights
    float* xs = smem + OKK * C;   // [64][128]  x[b, :, h, :]

    const int t = threadIdx.x;
    const int h = blockIdx.x;
    const int b = blockIdx.y;

    // ---- cooperative load: W_gen (576x64 fp32 = 144KB) ----
    {
        float4* Ws4 = reinterpret_cast<float4*>(Ws);
        const float4* Wg4 = reinterpret_cast<const float4*>(Wg);
        #pragma unroll
        for (int i = 0; i < 36; i++)                 // 9216 float4 / 256 threads
            Ws4[i * 256 + t] = Wg4[i * 256 + t];
    }
    // ---- cooperative load: x[b, :, h, :] (64x128 = 32KB) ----
    {
        float4* xs4w = reinterpret_cast<float4*>(xs);
        const float4* x4 = reinterpret_cast<const float4*>(x);
        const long chan4 = (long)(Hd * Wd / 4);      // 4096 float4 per channel
        const long base4 = (long)b * C * chan4 + (long)h * (Wd / 4);
        #pragma unroll
        for (int i = 0; i < 8; i++) {                // 2048 float4 / 256 threads
            int idx = i * 256 + t;
            int c   = idx >> 5;                      // Wd/4 == 32
            int w4  = idx & 31;
            xs4w[idx] = x4[base4 + (long)c * chan4 + w4];
        }
    }
    __syncthreads();

    const int wg   = t & 15;      // 16 w-groups x 8 pixels = 128
    const int cidx = t >> 4;      // 0..15; c = cidx + 16*ci
    const int w0   = wg * 8;

    const float4* xs4 = reinterpret_cast<const float4*>(xs);

    #pragma unroll 1
    for (int ci = 0; ci < 4; ci++) {
        const int c = cidx + 16 * ci;
        const float* wrow = Ws + (long)c * 9 * 64;   // 9 consecutive 64-wide rows

        float acc[9][8];
        #pragma unroll
        for (int p = 0; p < 9; p++)
            #pragma unroll
            for (int j = 0; j < 8; j++) acc[p][j] = 0.f;

        // ---- filter-generation GEMM: 9 taps x 8 pixels, K=64 ----
        #pragma unroll 8
        for (int k = 0; k < 64; k++) {
            float4 xa = xs4[k * 32 + wg * 2];
            float4 xb = xs4[k * 32 + wg * 2 + 1];
            float xv[8] = {xa.x, xa.y, xa.z, xa.w, xb.x, xb.y, xb.z, xb.w};
            #pragma unroll
            for (int p = 0; p < 9; p++) {
                float wv = wrow[p * 64 + k];         // warp-broadcast LDS
                #pragma unroll
                for (int j = 0; j < 8; j++)
                    acc[p][j] = fmaf(wv, xv[j], acc[p][j]);
            }
        }

        // ---- bias + ReLU ----
        #pragma unroll
        for (int p = 0; p < 9; p++) {
            float bb = bg[c * 9 + p];
            #pragma unroll
            for (int j = 0; j < 8; j++)
                acc[p][j] = fmaxf(acc[p][j] + bb, 0.f);
        }

        // ---- dynamic-filter combine with 3x3 patches ----
        float o[8];
        #pragma unroll
        for (int j = 0; j < 8; j++) o[j] = 0.f;

        const float* xc = x + (long)(b * C + c) * Hd * Wd;
        #pragma unroll
        for (int dh = 0; dh < 3; dh++) {
            const int hh = h - 1 + dh;
            float row[10];                            // x[.., hh, w0-1 .. w0+8]
            if (dh == 1) {
                const float* xr = xs + c * Wd;        // reuse smem row (always valid)
                #pragma unroll
                for (int r = 0; r < 10; r++) {
                    int ww = w0 - 1 + r;
                    row[r] = (ww >= 0 && ww < Wd) ? xr[ww] : 0.f;
                }
            } else if (hh >= 0 && hh < Hd) {
                const float* xr = xc + (long)hh * Wd;
                #pragma unroll
                for (int r = 0; r < 10; r++) {
                    int ww = w0 - 1 + r;
                    row[r] = (ww >= 0 && ww < Wd) ? xr[ww] : 0.f;
                }
            } else {
                #pragma unroll
                for (int r = 0; r < 10; r++) row[r] = 0.f;
            }
            #pragma unroll
            for (int j = 0; j < 8; j++)
                o[j] += acc[dh * 3 + 0][j] * row[j]
                      + acc[dh * 3 + 1][j] * row[j + 1]
                      + acc[dh * 3 + 2][j] * row[j + 2];
        }

        // ---- store 8 consecutive pixels (2x STG.128) ----
        float* op = out + ((long)(b * C + c) * Hd + h) * Wd + w0;
        float4 o0 = make_float4(o[0], o[1], o[2], o[3]);
        float4 o1 = make_float4(o[4], o[5], o[6], o[7]);
        reinterpret_cast<float4*>(op)[0] = o0;
        reinterpret_cast<float4*>(op)[1] = o1;
    }
}

extern "C" void kernel_launch(void* const* d_in, const int* in_sizes, int n_in,
                              void* d_out, int out_size)
{
    const float* x  = (const float*)d_in[0];
    const float* Wg = (const float*)d_in[1];
    const float* bg = (const float*)d_in[2];
    float* out = (float*)d_out;

    const int B = in_sizes[0] / (C * Hd * Wd);   // 8

    cudaFuncSetAttribute(acda_kernel,
                         cudaFuncAttributeMaxDynamicSharedMemorySize, SMEM_BYTES);
    dim3 grid(Hd, B);
    acda_kernel<<<grid, 256, SMEM_BYTES>>>(x, Wg, bg, out);
}

// round 6
// speedup vs baseline: 1.4329x; 1.4329x over previous
#include <cuda_runtime.h>
#include <cstdint>

// ACDA dynamic convolution via warp-level tf32 mma.sync (sm_80-baseline PTX —
// tcgen05 is rejected by this harness's compute_103 virtual arch).
// Per (b,h): F[576,128px] = W_gen[576,64] @ X[64,128px]; bias+ReLU; 3x3 combine.
// B=8, C=64, H=W=128.

static constexpr int CH = 64, Hd = 128, Wdim = 128;

// smem layout (bytes)
static constexpr int SM_WFRAG = 0;                       // 36 mt * 8 ks * 32 lanes * 16B = 147456
static constexpr int SM_FS    = 147456;                  // F chunk: [144][128] f32 = 73728
static constexpr int SM_BIAS  = 147456 + 73728;          // 576 f32
static constexpr int SMEM_BYTES = SM_BIAS + 2304;        // 223488

static __device__ __forceinline__ uint32_t f2tf(float f) {
    uint32_t u;
    asm("cvt.rna.tf32.f32 %0, %1;" : "=r"(u) : "f"(f));
    return u;
}

static __device__ __forceinline__ void mma_tf32(float* d, const uint32_t* a, const uint32_t* b) {
    asm volatile(
        "mma.sync.aligned.m16n8k8.row.col.f32.tf32.tf32.f32 "
        "{%0,%1,%2,%3}, {%4,%5,%6,%7}, {%8,%9}, {%0,%1,%2,%3};"
        : "+f"(d[0]), "+f"(d[1]), "+f"(d[2]), "+f"(d[3])
        : "r"(a[0]), "r"(a[1]), "r"(a[2]), "r"(a[3]), "r"(b[0]), "r"(b[1]));
}

__global__ __launch_bounds__(256, 1)
void acda_mma(const float* __restrict__ x,
              const float* __restrict__ Wg,
              const float* __restrict__ bg,
              float* __restrict__ out,
              int nUnits)
{
    extern __shared__ char smem[];
    uint32_t* Wfrag = reinterpret_cast<uint32_t*>(smem + SM_WFRAG);
    float*    Fs    = reinterpret_cast<float*>(smem + SM_FS);
    float*    bs    = reinterpret_cast<float*>(smem + SM_BIAS);

    const int t    = threadIdx.x;
    const int lane = t & 31;
    const int wid  = t >> 5;
    const int s     = wid & 3;    // n-strip: pixels [s*32, s*32+32)
    const int mhalf = wid >> 2;   // m-tile half within each chunk

    // ---- stage W_gen as tf32 A-fragments (once per CTA) ----
    // m16n8k8 A layout: a[r] at (row = lane/4 + 8*(r&1), col = lane%4 + 4*(r>>1))
    #pragma unroll 4
    for (int i = t; i < 576 * 64; i += 256) {
        int row = i >> 6, col = i & 63;
        int mt = row >> 4, rr = row & 15, ks = col >> 3, cc = col & 7;
        int ln = (rr & 7) * 4 + (cc & 3);
        int r  = (rr >> 3) + ((cc >> 2) << 1);
        Wfrag[((mt * 8 + ks) * 32 + ln) * 4 + r] = f2tf(Wg[i]);
    }
    for (int i = t; i < 576; i += 256) bs[i] = bg[i];
    __syncthreads();

    // epilogue thread mapping (fixed across chunks)
    const int ecl = t >> 4;           // channel-within-chunk 0..15
    const int ew0 = (t & 15) * 8;     // pixel-group base

    for (int u = blockIdx.x; u < nUnits; u += gridDim.x) {
        const int b = u >> 7;
        const int h = u & 127;

        // ---- load B fragments from global, once per unit ----
        // m16n8k8 B layout: b[r] at (k = lane%4 + 4r, n = lane/4)
        uint32_t bfr[4][8][2];
        {
            const float* xbh = x + (long)b * CH * Hd * Wdim + (long)h * Wdim;
            const int pxb = s * 32 + (lane >> 2);
            #pragma unroll 1
            for (int ks = 0; ks < 8; ks++) {
                #pragma unroll
                for (int r = 0; r < 2; r++) {
                    const int c = ks * 8 + (lane & 3) + 4 * r;
                    const float* xp = xbh + (long)c * Hd * Wdim + pxb;
                    #pragma unroll
                    for (int nt = 0; nt < 4; nt++)
                        bfr[nt][ks][r] = f2tf(__ldg(xp + nt * 8));
                }
            }
        }

        // ---- 4 chunks of 144 F-rows (16 whole channels = 9 m-tiles each) ----
        #pragma unroll 1
        for (int ch = 0; ch < 4; ch++) {
            __syncthreads();   // previous chunk's epilogue done reading Fs

            const int mtl0 = mhalf ? 5 : 0;
            const int mtlN = mhalf ? 4 : 5;
            #pragma unroll 1
            for (int i = 0; i < mtlN; i++) {
                const int mtl = mtl0 + i;
                const int mt  = ch * 9 + mtl;
                float acc[4][4];
                #pragma unroll
                for (int nt = 0; nt < 4; nt++)
                    #pragma unroll
                    for (int r = 0; r < 4; r++) acc[nt][r] = 0.f;

                const uint4* Af = reinterpret_cast<const uint4*>(Wfrag) + (mt * 8) * 32 + lane;
                #pragma unroll
                for (int ks = 0; ks < 8; ks++) {
                    uint4 av = Af[ks * 32];
                    uint32_t a[4] = {av.x, av.y, av.z, av.w};
                    #pragma unroll
                    for (int nt = 0; nt < 4; nt++)
                        mma_tf32(acc[nt], a, bfr[nt][ks]);
                }

                // D layout: c[0,1] at (row lane/4, col 2*(lane%4)+{0,1}); c[2,3] at row+8
                const int row  = mtl * 16 + (lane >> 2);
                const int colb = s * 32 + 2 * (lane & 3);
                #pragma unroll
                for (int nt = 0; nt < 4; nt++) {
                    const int col = colb + nt * 8;
                    *reinterpret_cast<float2*>(&Fs[row * 128 + col]) =
                        make_float2(acc[nt][0], acc[nt][1]);
                    *reinterpret_cast<float2*>(&Fs[(row + 8) * 128 + col]) =
                        make_float2(acc[nt][2], acc[nt][3]);
                }
            }
            __syncthreads();   // F chunk complete

            // ---- bias + ReLU + 3x3 dynamic-filter combine ----
            const int c = ch * 16 + ecl;      // global channel

            float o[8];
            #pragma unroll
            for (int j = 0; j < 8; j++) o[j] = 0.f;

            const float* xc = x + (long)(b * CH + c) * Hd * Wdim;
            #pragma unroll
            for (int dh = 0; dh < 3; dh++) {
                const int hh = h - 1 + dh;
                float row[10];
                if (hh >= 0 && hh < Hd) {
                    const float* xr = xc + (long)hh * Wdim;
                    #pragma unroll
                    for (int q = 0; q < 10; q++) {
                        int ww = ew0 - 1 + q;
                        row[q] = (ww >= 0 && ww < 128) ? __ldg(xr + ww) : 0.f;
                    }
                } else {
                    #pragma unroll
                    for (int q = 0; q < 10; q++) row[q] = 0.f;
                }
                #pragma unroll
                for (int p = 0; p < 3; p++) {
                    const int tap = dh * 3 + p;
                    const float bb = bs[c * 9 + tap];
                    const float* fRow = Fs + (ecl * 9 + tap) * 128 + ew0;
                    #pragma unroll
                    for (int j = 0; j < 8; j++) {
                        float f = fmaxf(fRow[j] + bb, 0.f);
                        o[j] = fmaf(f, row[j + p], o[j]);
                    }
                }
            }

            float* op = out + ((long)(b * CH + c) * Hd + h) * Wdim + ew0;
            *reinterpret_cast<float4*>(op)     = make_float4(o[0], o[1], o[2], o[3]);
            *reinterpret_cast<float4*>(op + 4) = make_float4(o[4], o[5], o[6], o[7]);
        }
    }
}

extern "C" void kernel_launch(void* const* d_in, const int* in_sizes, int n_in,
                              void* d_out, int out_size)
{
    const float* x  = (const float*)d_in[0];
    const float* Wg = (const float*)d_in[1];
    const float* bg = (const float*)d_in[2];
    float* out = (float*)d_out;

    const int B = in_sizes[0] / (CH * Hd * Wdim);
    const int nUnits = B * Hd;

    cudaFuncSetAttribute(acda_mma, cudaFuncAttributeMaxDynamicSharedMemorySize, SMEM_BYTES);
    acda_mma<<<148, 256, SMEM_BYTES>>>(x, Wg, bg, out, nUnits);
}